// round 10
// baseline (speedup 1.0000x reference)
#include <cuda_runtime.h>
#include <cuda_fp16.h>

#define NN 50000
#define DD 128
#define EE 800000

// Scratch (__device__ globals; no allocations allowed)
__device__ float  g_h    [NN * DD];            // GEMM output (fp32)
__device__ __align__(16) __half g_hh[NN * DD]; // GEMM output (fp16 copy for gathers)
__device__ float  g_z    [NN * DD];            // layer-1 activation
__device__ float  g_dinv [NN];                 // weighted degree -> d^{-1/2}
__device__ int    g_cnt  [NN];                 // in-degree counts
__device__ int    g_rowptr[NN + 1];            // CSR row pointers (by dst)
__device__ int    g_cursor[NN];                // placement cursors
__device__ int2   g_sd   [EE];                 // packed (src, dst)
__device__ int2   g_edge [EE];                 // CSR-ordered (src, norm-bits)
__device__ int    g_bsum [64];
__device__ int    g_boff [64];
__device__ int    g_is64;
__device__ float  g_w1hi[DD * DD], g_w1lo[DD * DD];
__device__ float  g_w2hi[DD * DD], g_w2lo[DD * DD];

// ---------------- TF32 helper ----------------
__device__ __forceinline__ unsigned f2tf32(float f) {
    unsigned u;
    asm("cvt.rna.tf32.f32 %0, %1;" : "=r"(u) : "f"(f));
    return u;
}

// ---------------- init (fused detect + per-node init) ----------------
__global__ void k_init(const int* __restrict__ ei32, int n) {
    int i = blockIdx.x * blockDim.x + threadIdx.x;
    if (i < n) {
        g_dinv[i] = 1.0f;
        g_cnt[i]  = 0;
    }
    if (blockIdx.x == 0 && threadIdx.x == 0) {
        int acc = 0;
#pragma unroll
        for (int k = 0; k < 64; ++k) acc |= ei32[2 * k + 1];
        g_is64 = (acc == 0) ? 1 : 0;
    }
}

// ---------------- split W1/W2 into tf32 hi/lo ----------------
__global__ void k_splitw(const float* __restrict__ W1,
                         const float* __restrict__ W2) {
    int i = blockIdx.x * blockDim.x + threadIdx.x;
    if (i >= DD * DD) return;
    float w1 = W1[i];
    float h1 = __uint_as_float(f2tf32(w1));
    g_w1hi[i] = h1;
    g_w1lo[i] = __uint_as_float(f2tf32(w1 - h1));
    float w2 = W2[i];
    float h2 = __uint_as_float(f2tf32(w2));
    g_w2hi[i] = h2;
    g_w2lo[i] = __uint_as_float(f2tf32(w2 - h2));
}

// ---------------- convert + degree + histogram ----------------
__global__ void k_convert(const int* __restrict__ ei32,
                          const float* __restrict__ ew, int E) {
    int e = blockIdx.x * blockDim.x + threadIdx.x;
    if (e >= E) return;
    int s, d;
    if (g_is64) {
        s = ei32[2 * e];
        d = ei32[2 * (E + e)];
    } else {
        s = ei32[e];
        d = ei32[E + e];
    }
    g_sd[e] = make_int2(s, d);
    atomicAdd(&g_dinv[d], ew[e]);
    atomicAdd(&g_cnt[d], 1);
}

// ---------------- multi-block scan, stage 1 ----------------
__global__ void k_bsum(int N) {
    __shared__ int sh[32];
    int tid  = threadIdx.x;
    int base = blockIdx.x * 1024;
    int v = 0;
#pragma unroll
    for (int j = 0; j < 4; ++j) {
        int i = base + tid + j * 256;
        v += (i < N) ? g_cnt[i] : 0;
    }
#pragma unroll
    for (int o = 16; o > 0; o >>= 1)
        v += __shfl_down_sync(0xFFFFFFFFu, v, o);
    if ((tid & 31) == 0) sh[tid >> 5] = v;
    __syncthreads();
    if (tid < 8) {
        int t = sh[tid];
#pragma unroll
        for (int o = 4; o > 0; o >>= 1)
            t += __shfl_down_sync(0xFFu, t, o);
        if (tid == 0) g_bsum[blockIdx.x] = t;
    }
}

// ---------------- stage 2 ----------------
__global__ void k_bscan(int nb, int N) {
    int tid  = threadIdx.x;   // 64
    int lane = tid & 31;
    int w    = tid >> 5;
    __shared__ int wtot[2];
    int v = (tid < nb) ? g_bsum[tid] : 0;
    int s = v;
#pragma unroll
    for (int o = 1; o < 32; o <<= 1) {
        int t = __shfl_up_sync(0xFFFFFFFFu, s, o);
        if (lane >= o) s += t;
    }
    if (lane == 31) wtot[w] = s;
    __syncthreads();
    int incl = s + ((w == 1) ? wtot[0] : 0);
    if (tid < nb) g_boff[tid] = incl - v;
    if (tid == 63) g_rowptr[N] = wtot[0] + wtot[1];
}

// ---------------- stage 3 (+ fused dinv finalize) ----------------
__global__ void k_rowptr(int N) {
    __shared__ int wsum[32];
    int tid  = threadIdx.x;   // 1024
    int lane = tid & 31;
    int wid  = tid >> 5;
    int i = blockIdx.x * 1024 + tid;
    int v = (i < N) ? g_cnt[i] : 0;
    int s = v;
#pragma unroll
    for (int o = 1; o < 32; o <<= 1) {
        int t = __shfl_up_sync(0xFFFFFFFFu, s, o);
        if (lane >= o) s += t;
    }
    if (lane == 31) wsum[wid] = s;
    __syncthreads();
    if (wid == 0) {
        int ws = wsum[lane];
#pragma unroll
        for (int o = 1; o < 32; o <<= 1) {
            int t = __shfl_up_sync(0xFFFFFFFFu, ws, o);
            if (lane >= o) ws += t;
        }
        wsum[lane] = ws;
    }
    __syncthreads();
    int excl = s - v + ((wid > 0) ? wsum[wid - 1] : 0) + g_boff[blockIdx.x];
    if (i < N) {
        g_rowptr[i] = excl;
        g_cursor[i] = excl;
        float deg = g_dinv[i];
        g_dinv[i] = (deg > 0.0f) ? rsqrtf(deg) : 0.0f;
    }
}

// -------- place edges into CSR order with packed (src, norm) record --------
__global__ void k_place(const float* __restrict__ ew, int E) {
    int e = blockIdx.x * blockDim.x + threadIdx.x;
    if (e >= E) return;
    int2 sd = g_sd[e];
    float nrm = g_dinv[sd.x] * ew[e] * g_dinv[sd.y];
    int pos = atomicAdd(&g_cursor[sd.y], 1);
    g_edge[pos] = make_int2(sd.x, __float_as_int(nrm));
}

// ---------------- MMA macro ----------------
#define MMA_TF32(d, a0, a1, a2, a3, b0, b1)                                   \
    asm volatile(                                                             \
        "mma.sync.aligned.m16n8k8.row.col.f32.tf32.tf32.f32 "                 \
        "{%0,%1,%2,%3}, {%4,%5,%6,%7}, {%8,%9}, {%0,%1,%2,%3};"               \
        : "+f"(d[0]), "+f"(d[1]), "+f"(d[2]), "+f"(d[3])                      \
        : "r"(a0), "r"(a1), "r"(a2), "r"(a3), "r"(b0), "r"(b1))

// ------- GEMM: g_h / g_hh = X @ W via 3xTF32 tensor-core mma -------
__global__ void __launch_bounds__(256)
k_gemm(const float* __restrict__ Xext, int use_gz, int N) {
    __shared__ float xs_hi[128][20], xs_lo[128][20];
    __shared__ float ws_hi[16][132], ws_lo[16][132];

    const float* __restrict__ X   = use_gz ? g_z : Xext;
    const float* __restrict__ Whi = use_gz ? g_w2hi : g_w1hi;
    const float* __restrict__ Wlo = use_gz ? g_w2lo : g_w1lo;

    int tid  = threadIdx.x;
    int lane = tid & 31;
    int warp = tid >> 5;
    int grp  = lane >> 2;
    int tig  = lane & 3;
    int wm   = warp & 3;
    int wn   = warp >> 2;
    int r0   = blockIdx.x * 128;

    float acc[2][8][4];
#pragma unroll
    for (int mt = 0; mt < 2; ++mt)
#pragma unroll
        for (int nt = 0; nt < 8; ++nt)
#pragma unroll
            for (int c = 0; c < 4; ++c) acc[mt][nt][c] = 0.0f;

    for (int chunk = 0; chunk < 8; ++chunk) {
        int k0 = chunk * 16;
#pragma unroll
        for (int rep = 0; rep < 2; ++rep) {
            int q   = tid + rep * 256;
            int row = q >> 2;
            int qc  = q & 3;
            float4 v = make_float4(0.f, 0.f, 0.f, 0.f);
            if (r0 + row < N)
                v = *(const float4*)&X[(r0 + row) * DD + k0 + qc * 4];
            float e[4] = {v.x, v.y, v.z, v.w};
#pragma unroll
            for (int j = 0; j < 4; ++j) {
                float hi = __uint_as_float(f2tf32(e[j]));
                xs_hi[row][qc * 4 + j] = hi;
                xs_lo[row][qc * 4 + j] = __uint_as_float(f2tf32(e[j] - hi));
            }
        }
#pragma unroll
        for (int rep = 0; rep < 2; ++rep) {
            int q  = tid + rep * 256;
            int kk = q >> 5;
            int qc = q & 31;
            *(float4*)&ws_hi[kk][qc * 4] = *(const float4*)&Whi[(k0 + kk) * DD + qc * 4];
            *(float4*)&ws_lo[kk][qc * 4] = *(const float4*)&Wlo[(k0 + kk) * DD + qc * 4];
        }
        __syncthreads();

#pragma unroll
        for (int step = 0; step < 2; ++step) {
            int ks = step * 8;
            unsigned a_hi[2][4], a_lo[2][4];
#pragma unroll
            for (int mt = 0; mt < 2; ++mt) {
                int ar = wm * 32 + mt * 16 + grp;
                a_hi[mt][0] = __float_as_uint(xs_hi[ar    ][ks + tig    ]);
                a_hi[mt][1] = __float_as_uint(xs_hi[ar + 8][ks + tig    ]);
                a_hi[mt][2] = __float_as_uint(xs_hi[ar    ][ks + tig + 4]);
                a_hi[mt][3] = __float_as_uint(xs_hi[ar + 8][ks + tig + 4]);
                a_lo[mt][0] = __float_as_uint(xs_lo[ar    ][ks + tig    ]);
                a_lo[mt][1] = __float_as_uint(xs_lo[ar + 8][ks + tig    ]);
                a_lo[mt][2] = __float_as_uint(xs_lo[ar    ][ks + tig + 4]);
                a_lo[mt][3] = __float_as_uint(xs_lo[ar + 8][ks + tig + 4]);
            }
#pragma unroll
            for (int nt = 0; nt < 8; ++nt) {
                int c0 = wn * 64 + nt * 8 + grp;
                unsigned b_hi0 = __float_as_uint(ws_hi[ks + tig    ][c0]);
                unsigned b_hi1 = __float_as_uint(ws_hi[ks + tig + 4][c0]);
                unsigned b_lo0 = __float_as_uint(ws_lo[ks + tig    ][c0]);
                unsigned b_lo1 = __float_as_uint(ws_lo[ks + tig + 4][c0]);
#pragma unroll
                for (int mt = 0; mt < 2; ++mt) {
                    MMA_TF32(acc[mt][nt], a_hi[mt][0], a_hi[mt][1], a_hi[mt][2], a_hi[mt][3], b_hi0, b_hi1);
                    MMA_TF32(acc[mt][nt], a_hi[mt][0], a_hi[mt][1], a_hi[mt][2], a_hi[mt][3], b_lo0, b_lo1);
                    MMA_TF32(acc[mt][nt], a_lo[mt][0], a_lo[mt][1], a_lo[mt][2], a_lo[mt][3], b_hi0, b_hi1);
                }
            }
        }
        __syncthreads();
    }

#pragma unroll
    for (int mt = 0; mt < 2; ++mt) {
#pragma unroll
        for (int nt = 0; nt < 8; ++nt) {
            int row = r0 + wm * 32 + mt * 16 + grp;
            int col = wn * 64 + nt * 8 + 2 * tig;
            if (row < N) {
                *(float2*)&g_h[row * DD + col] = make_float2(acc[mt][nt][0], acc[mt][nt][1]);
                *(__half2*)&g_hh[row * DD + col] = __floats2half2_rn(acc[mt][nt][0], acc[mt][nt][1]);
            }
            if (row + 8 < N) {
                *(float2*)&g_h[(row + 8) * DD + col] = make_float2(acc[mt][nt][2], acc[mt][nt][3]);
                *(__half2*)&g_hh[(row + 8) * DD + col] = __floats2half2_rn(acc[mt][nt][2], acc[mt][nt][3]);
            }
        }
    }
}

// -------- fused aggregate: warp/node; fp16 gathers, fp32 self-loop + accum --------
__global__ void k_aggregate(const float* __restrict__ b,
                            const float* __restrict__ a,
                            float* __restrict__ Oext, int use_ext, int N) {
    int node = (blockIdx.x * blockDim.x + threadIdx.x) >> 5;
    if (node >= N) return;
    int lane = threadIdx.x & 31;

    const uint2* __restrict__ hh = (const uint2*)g_hh;   // 4 halfs per lane
    float di  = g_dinv[node];
    float di2 = di * di;

    float4 hv = ((const float4*)g_h)[node * 32 + lane];  // fp32 self-loop
    float4 bb = ((const float4*)b)[lane];
    float4 acc;
    acc.x = fmaf(di2, hv.x, bb.x);
    acc.y = fmaf(di2, hv.y, bb.y);
    acc.z = fmaf(di2, hv.z, bb.z);
    acc.w = fmaf(di2, hv.w, bb.w);

    int i   = g_rowptr[node];
    int end = g_rowptr[node + 1];

#pragma unroll 1
    for (; i + 4 <= end; i += 4) {
        int2 e0 = g_edge[i],     e1 = g_edge[i + 1];
        int2 e2 = g_edge[i + 2], e3 = g_edge[i + 3];
        uint2 p0 = hh[e0.x * 32 + lane];
        uint2 p1 = hh[e1.x * 32 + lane];
        uint2 p2 = hh[e2.x * 32 + lane];
        uint2 p3 = hh[e3.x * 32 + lane];
        float w0 = __int_as_float(e0.y), w1 = __int_as_float(e1.y);
        float w2 = __int_as_float(e2.y), w3 = __int_as_float(e3.y);
        float2 f0a = __half22float2(*(__half2*)&p0.x), f0b = __half22float2(*(__half2*)&p0.y);
        float2 f1a = __half22float2(*(__half2*)&p1.x), f1b = __half22float2(*(__half2*)&p1.y);
        float2 f2a = __half22float2(*(__half2*)&p2.x), f2b = __half22float2(*(__half2*)&p2.y);
        float2 f3a = __half22float2(*(__half2*)&p3.x), f3b = __half22float2(*(__half2*)&p3.y);
        acc.x = fmaf(w0, f0a.x, acc.x); acc.y = fmaf(w0, f0a.y, acc.y);
        acc.z = fmaf(w0, f0b.x, acc.z); acc.w = fmaf(w0, f0b.y, acc.w);
        acc.x = fmaf(w1, f1a.x, acc.x); acc.y = fmaf(w1, f1a.y, acc.y);
        acc.z = fmaf(w1, f1b.x, acc.z); acc.w = fmaf(w1, f1b.y, acc.w);
        acc.x = fmaf(w2, f2a.x, acc.x); acc.y = fmaf(w2, f2a.y, acc.y);
        acc.z = fmaf(w2, f2b.x, acc.z); acc.w = fmaf(w2, f2b.y, acc.w);
        acc.x = fmaf(w3, f3a.x, acc.x); acc.y = fmaf(w3, f3a.y, acc.y);
        acc.z = fmaf(w3, f3b.x, acc.z); acc.w = fmaf(w3, f3b.y, acc.w);
    }
    for (; i < end; ++i) {
        int2 e = g_edge[i];
        float w = __int_as_float(e.y);
        uint2 p = hh[e.x * 32 + lane];
        float2 fa = __half22float2(*(__half2*)&p.x);
        float2 fb = __half22float2(*(__half2*)&p.y);
        acc.x = fmaf(w, fa.x, acc.x); acc.y = fmaf(w, fa.y, acc.y);
        acc.z = fmaf(w, fb.x, acc.z); acc.w = fmaf(w, fb.y, acc.w);
    }

    float4 aa = ((const float4*)a)[lane];
    acc.x = (acc.x > 0.f) ? acc.x : aa.x * acc.x;
    acc.y = (acc.y > 0.f) ? acc.y : aa.y * acc.y;
    acc.z = (acc.z > 0.f) ? acc.z : aa.z * acc.z;
    acc.w = (acc.w > 0.f) ? acc.w : aa.w * acc.w;

    float4* Z = use_ext ? (float4*)Oext : (float4*)g_z;
    Z[node * 32 + lane] = acc;
}

// -------- launch --------
extern "C" void kernel_launch(void* const* d_in, const int* in_sizes, int n_in,
                              void* d_out, int out_size) {
    const float* x  = (const float*)d_in[0];
    const int*   ei = (const int*)d_in[1];
    const float* ew = (const float*)d_in[2];
    const float* W1 = (const float*)d_in[3];
    const float* b1 = (const float*)d_in[4];
    const float* a1 = (const float*)d_in[5];
    const float* W2 = (const float*)d_in[6];
    const float* b2 = (const float*)d_in[7];
    const float* a2 = (const float*)d_in[8];
    float* out = (float*)d_out;

    const int N = in_sizes[0] / DD;   // 50000
    const int E = in_sizes[2];        // 800000
    const int nb = (N + 1023) / 1024; // 49

    // ---- preprocessing ----
    k_init<<<(N + 255) / 256, 256>>>(ei, N);
    k_splitw<<<(DD * DD + 255) / 256, 256>>>(W1, W2);
    k_convert<<<(E + 255) / 256, 256>>>(ei, ew, E);
    k_bsum<<<nb, 256>>>(N);
    k_bscan<<<1, 64>>>(nb, N);
    k_rowptr<<<nb, 1024>>>(N);
    k_place<<<(E + 255) / 256, 256>>>(ew, E);

    const int gemm_grid = (N + 127) / 128;
    const int agg_grid  = (N * 32 + 255) / 256;

    // ---- layer 1 ----
    k_gemm<<<gemm_grid, 256>>>(x, 0, N);
    k_aggregate<<<agg_grid, 256>>>(b1, a1, out, 0, N);

    // ---- layer 2 ----
    k_gemm<<<gemm_grid, 256>>>(nullptr, 1, N);
    k_aggregate<<<agg_grid, 256>>>(b2, a2, out, 1, N);
}

// round 11
// speedup vs baseline: 1.1718x; 1.1718x over previous
#include <cuda_runtime.h>
#include <cuda_fp16.h>

#define NN 50000
#define DD 128
#define EE 800000

// Scratch (__device__ globals; no allocations allowed)
__device__ __align__(16) __half g_hh[NN * DD]; // GEMM output (fp16, gathered)
__device__ float  g_z    [NN * DD];            // layer-1 activation (fp32)
__device__ float  g_dinv [NN];                 // weighted degree -> d^{-1/2}
__device__ int    g_cnt  [NN];                 // in-degree counts
__device__ int    g_rowptr[NN + 1];            // CSR row pointers (by dst)
__device__ int    g_cursor[NN];                // placement cursors
__device__ int2   g_sd   [EE];                 // packed (src, dst)
__device__ int2   g_edge [EE];                 // CSR-ordered (src, norm-bits)
__device__ int    g_bsum [64];
__device__ int    g_boff [64];
__device__ int    g_is64;
__device__ float  g_w1hi[DD * DD], g_w1lo[DD * DD];
__device__ float  g_w2hi[DD * DD], g_w2lo[DD * DD];

// ---------------- TF32 helper ----------------
__device__ __forceinline__ unsigned f2tf32(float f) {
    unsigned u;
    asm("cvt.rna.tf32.f32 %0, %1;" : "=r"(u) : "f"(f));
    return u;
}

// ---------------- init (fused detect + per-node init) ----------------
__global__ void k_init(const int* __restrict__ ei32, int n) {
    int i = blockIdx.x * blockDim.x + threadIdx.x;
    if (i < n) {
        g_dinv[i] = 1.0f;
        g_cnt[i]  = 0;
    }
    if (blockIdx.x == 0 && threadIdx.x == 0) {
        int acc = 0;
#pragma unroll
        for (int k = 0; k < 64; ++k) acc |= ei32[2 * k + 1];
        g_is64 = (acc == 0) ? 1 : 0;
    }
}

// ---------------- split W1/W2 into tf32 hi/lo ----------------
__global__ void k_splitw(const float* __restrict__ W1,
                         const float* __restrict__ W2) {
    int i = blockIdx.x * blockDim.x + threadIdx.x;
    if (i >= DD * DD) return;
    float w1 = W1[i];
    float h1 = __uint_as_float(f2tf32(w1));
    g_w1hi[i] = h1;
    g_w1lo[i] = __uint_as_float(f2tf32(w1 - h1));
    float w2 = W2[i];
    float h2 = __uint_as_float(f2tf32(w2));
    g_w2hi[i] = h2;
    g_w2lo[i] = __uint_as_float(f2tf32(w2 - h2));
}

// ---------------- convert + degree + histogram ----------------
__global__ void k_convert(const int* __restrict__ ei32,
                          const float* __restrict__ ew, int E) {
    int e = blockIdx.x * blockDim.x + threadIdx.x;
    if (e >= E) return;
    int s, d;
    if (g_is64) {
        s = ei32[2 * e];
        d = ei32[2 * (E + e)];
    } else {
        s = ei32[e];
        d = ei32[E + e];
    }
    g_sd[e] = make_int2(s, d);
    atomicAdd(&g_dinv[d], ew[e]);
    atomicAdd(&g_cnt[d], 1);
}

// ---------------- multi-block scan, stage 1 ----------------
__global__ void k_bsum(int N) {
    __shared__ int sh[32];
    int tid  = threadIdx.x;
    int base = blockIdx.x * 1024;
    int v = 0;
#pragma unroll
    for (int j = 0; j < 4; ++j) {
        int i = base + tid + j * 256;
        v += (i < N) ? g_cnt[i] : 0;
    }
#pragma unroll
    for (int o = 16; o > 0; o >>= 1)
        v += __shfl_down_sync(0xFFFFFFFFu, v, o);
    if ((tid & 31) == 0) sh[tid >> 5] = v;
    __syncthreads();
    if (tid < 8) {
        int t = sh[tid];
#pragma unroll
        for (int o = 4; o > 0; o >>= 1)
            t += __shfl_down_sync(0xFFu, t, o);
        if (tid == 0) g_bsum[blockIdx.x] = t;
    }
}

// ---------------- stage 2 ----------------
__global__ void k_bscan(int nb, int N) {
    int tid  = threadIdx.x;   // 64
    int lane = tid & 31;
    int w    = tid >> 5;
    __shared__ int wtot[2];
    int v = (tid < nb) ? g_bsum[tid] : 0;
    int s = v;
#pragma unroll
    for (int o = 1; o < 32; o <<= 1) {
        int t = __shfl_up_sync(0xFFFFFFFFu, s, o);
        if (lane >= o) s += t;
    }
    if (lane == 31) wtot[w] = s;
    __syncthreads();
    int incl = s + ((w == 1) ? wtot[0] : 0);
    if (tid < nb) g_boff[tid] = incl - v;
    if (tid == 63) g_rowptr[N] = wtot[0] + wtot[1];
}

// ---------------- stage 3 (+ fused dinv finalize) ----------------
__global__ void k_rowptr(int N) {
    __shared__ int wsum[32];
    int tid  = threadIdx.x;   // 1024
    int lane = tid & 31;
    int wid  = tid >> 5;
    int i = blockIdx.x * 1024 + tid;
    int v = (i < N) ? g_cnt[i] : 0;
    int s = v;
#pragma unroll
    for (int o = 1; o < 32; o <<= 1) {
        int t = __shfl_up_sync(0xFFFFFFFFu, s, o);
        if (lane >= o) s += t;
    }
    if (lane == 31) wsum[wid] = s;
    __syncthreads();
    if (wid == 0) {
        int ws = wsum[lane];
#pragma unroll
        for (int o = 1; o < 32; o <<= 1) {
            int t = __shfl_up_sync(0xFFFFFFFFu, ws, o);
            if (lane >= o) ws += t;
        }
        wsum[lane] = ws;
    }
    __syncthreads();
    int excl = s - v + ((wid > 0) ? wsum[wid - 1] : 0) + g_boff[blockIdx.x];
    if (i < N) {
        g_rowptr[i] = excl;
        g_cursor[i] = excl;
        float deg = g_dinv[i];
        g_dinv[i] = (deg > 0.0f) ? rsqrtf(deg) : 0.0f;
    }
}

// -------- place edges into CSR order with packed (src, norm) record --------
__global__ void k_place(const float* __restrict__ ew, int E) {
    int e = blockIdx.x * blockDim.x + threadIdx.x;
    if (e >= E) return;
    int2 sd = g_sd[e];
    float nrm = g_dinv[sd.x] * ew[e] * g_dinv[sd.y];
    int pos = atomicAdd(&g_cursor[sd.y], 1);
    g_edge[pos] = make_int2(sd.x, __float_as_int(nrm));
}

// ---------------- MMA macro ----------------
#define MMA_TF32(d, a0, a1, a2, a3, b0, b1)                                   \
    asm volatile(                                                             \
        "mma.sync.aligned.m16n8k8.row.col.f32.tf32.tf32.f32 "                 \
        "{%0,%1,%2,%3}, {%4,%5,%6,%7}, {%8,%9}, {%0,%1,%2,%3};"               \
        : "+f"(d[0]), "+f"(d[1]), "+f"(d[2]), "+f"(d[3])                      \
        : "r"(a0), "r"(a1), "r"(a2), "r"(a3), "r"(b0), "r"(b1))

// ------- GEMM: g_hh = fp16(X @ W) via 3xTF32 tensor-core mma -------
__global__ void __launch_bounds__(256)
k_gemm(const float* __restrict__ Xext, int use_gz, int N) {
    __shared__ float xs_hi[128][20], xs_lo[128][20];
    __shared__ float ws_hi[16][132], ws_lo[16][132];

    const float* __restrict__ X   = use_gz ? g_z : Xext;
    const float* __restrict__ Whi = use_gz ? g_w2hi : g_w1hi;
    const float* __restrict__ Wlo = use_gz ? g_w2lo : g_w1lo;

    int tid  = threadIdx.x;
    int lane = tid & 31;
    int warp = tid >> 5;
    int grp  = lane >> 2;
    int tig  = lane & 3;
    int wm   = warp & 3;
    int wn   = warp >> 2;
    int r0   = blockIdx.x * 128;

    float acc[2][8][4];
#pragma unroll
    for (int mt = 0; mt < 2; ++mt)
#pragma unroll
        for (int nt = 0; nt < 8; ++nt)
#pragma unroll
            for (int c = 0; c < 4; ++c) acc[mt][nt][c] = 0.0f;

    for (int chunk = 0; chunk < 8; ++chunk) {
        int k0 = chunk * 16;
#pragma unroll
        for (int rep = 0; rep < 2; ++rep) {
            int q   = tid + rep * 256;
            int row = q >> 2;
            int qc  = q & 3;
            float4 v = make_float4(0.f, 0.f, 0.f, 0.f);
            if (r0 + row < N)
                v = *(const float4*)&X[(r0 + row) * DD + k0 + qc * 4];
            float e[4] = {v.x, v.y, v.z, v.w};
#pragma unroll
            for (int j = 0; j < 4; ++j) {
                float hi = __uint_as_float(f2tf32(e[j]));
                xs_hi[row][qc * 4 + j] = hi;
                xs_lo[row][qc * 4 + j] = __uint_as_float(f2tf32(e[j] - hi));
            }
        }
#pragma unroll
        for (int rep = 0; rep < 2; ++rep) {
            int q  = tid + rep * 256;
            int kk = q >> 5;
            int qc = q & 31;
            *(float4*)&ws_hi[kk][qc * 4] = *(const float4*)&Whi[(k0 + kk) * DD + qc * 4];
            *(float4*)&ws_lo[kk][qc * 4] = *(const float4*)&Wlo[(k0 + kk) * DD + qc * 4];
        }
        __syncthreads();

#pragma unroll
        for (int step = 0; step < 2; ++step) {
            int ks = step * 8;
            unsigned a_hi[2][4], a_lo[2][4];
#pragma unroll
            for (int mt = 0; mt < 2; ++mt) {
                int ar = wm * 32 + mt * 16 + grp;
                a_hi[mt][0] = __float_as_uint(xs_hi[ar    ][ks + tig    ]);
                a_hi[mt][1] = __float_as_uint(xs_hi[ar + 8][ks + tig    ]);
                a_hi[mt][2] = __float_as_uint(xs_hi[ar    ][ks + tig + 4]);
                a_hi[mt][3] = __float_as_uint(xs_hi[ar + 8][ks + tig + 4]);
                a_lo[mt][0] = __float_as_uint(xs_lo[ar    ][ks + tig    ]);
                a_lo[mt][1] = __float_as_uint(xs_lo[ar + 8][ks + tig    ]);
                a_lo[mt][2] = __float_as_uint(xs_lo[ar    ][ks + tig + 4]);
                a_lo[mt][3] = __float_as_uint(xs_lo[ar + 8][ks + tig + 4]);
            }
#pragma unroll
            for (int nt = 0; nt < 8; ++nt) {
                int c0 = wn * 64 + nt * 8 + grp;
                unsigned b_hi0 = __float_as_uint(ws_hi[ks + tig    ][c0]);
                unsigned b_hi1 = __float_as_uint(ws_hi[ks + tig + 4][c0]);
                unsigned b_lo0 = __float_as_uint(ws_lo[ks + tig    ][c0]);
                unsigned b_lo1 = __float_as_uint(ws_lo[ks + tig + 4][c0]);
#pragma unroll
                for (int mt = 0; mt < 2; ++mt) {
                    MMA_TF32(acc[mt][nt], a_hi[mt][0], a_hi[mt][1], a_hi[mt][2], a_hi[mt][3], b_hi0, b_hi1);
                    MMA_TF32(acc[mt][nt], a_hi[mt][0], a_hi[mt][1], a_hi[mt][2], a_hi[mt][3], b_lo0, b_lo1);
                    MMA_TF32(acc[mt][nt], a_lo[mt][0], a_lo[mt][1], a_lo[mt][2], a_lo[mt][3], b_hi0, b_hi1);
                }
            }
        }
        __syncthreads();
    }

#pragma unroll
    for (int mt = 0; mt < 2; ++mt) {
#pragma unroll
        for (int nt = 0; nt < 8; ++nt) {
            int row = r0 + wm * 32 + mt * 16 + grp;
            int col = wn * 64 + nt * 8 + 2 * tig;
            if (row < N)
                *(__half2*)&g_hh[row * DD + col] =
                    __floats2half2_rn(acc[mt][nt][0], acc[mt][nt][1]);
            if (row + 8 < N)
                *(__half2*)&g_hh[(row + 8) * DD + col] =
                    __floats2half2_rn(acc[mt][nt][2], acc[mt][nt][3]);
        }
    }
}

// -------- fused aggregate: warp/node; fp16 gathers, fp32 accum --------
__global__ void k_aggregate(const float* __restrict__ b,
                            const float* __restrict__ a,
                            float* __restrict__ Oext, int use_ext, int N) {
    int node = (blockIdx.x * blockDim.x + threadIdx.x) >> 5;
    if (node >= N) return;
    int lane = threadIdx.x & 31;

    const uint2* __restrict__ hh = (const uint2*)g_hh;   // 4 halfs per lane
    float di  = g_dinv[node];
    float di2 = di * di;

    uint2 ps = hh[node * 32 + lane];                     // self-loop row
    float2 sa = __half22float2(*(__half2*)&ps.x);
    float2 sb = __half22float2(*(__half2*)&ps.y);
    float4 bb = ((const float4*)b)[lane];
    float4 acc;
    acc.x = fmaf(di2, sa.x, bb.x);
    acc.y = fmaf(di2, sa.y, bb.y);
    acc.z = fmaf(di2, sb.x, bb.z);
    acc.w = fmaf(di2, sb.y, bb.w);

    int i   = g_rowptr[node];
    int end = g_rowptr[node + 1];

    for (; i + 4 <= end; i += 4) {
        int2 e0 = g_edge[i],     e1 = g_edge[i + 1];
        int2 e2 = g_edge[i + 2], e3 = g_edge[i + 3];
        uint2 p0 = hh[e0.x * 32 + lane];
        uint2 p1 = hh[e1.x * 32 + lane];
        uint2 p2 = hh[e2.x * 32 + lane];
        uint2 p3 = hh[e3.x * 32 + lane];
        float w0 = __int_as_float(e0.y), w1 = __int_as_float(e1.y);
        float w2 = __int_as_float(e2.y), w3 = __int_as_float(e3.y);
        float2 f0a = __half22float2(*(__half2*)&p0.x), f0b = __half22float2(*(__half2*)&p0.y);
        float2 f1a = __half22float2(*(__half2*)&p1.x), f1b = __half22float2(*(__half2*)&p1.y);
        float2 f2a = __half22float2(*(__half2*)&p2.x), f2b = __half22float2(*(__half2*)&p2.y);
        float2 f3a = __half22float2(*(__half2*)&p3.x), f3b = __half22float2(*(__half2*)&p3.y);
        acc.x = fmaf(w0, f0a.x, acc.x); acc.y = fmaf(w0, f0a.y, acc.y);
        acc.z = fmaf(w0, f0b.x, acc.z); acc.w = fmaf(w0, f0b.y, acc.w);
        acc.x = fmaf(w1, f1a.x, acc.x); acc.y = fmaf(w1, f1a.y, acc.y);
        acc.z = fmaf(w1, f1b.x, acc.z); acc.w = fmaf(w1, f1b.y, acc.w);
        acc.x = fmaf(w2, f2a.x, acc.x); acc.y = fmaf(w2, f2a.y, acc.y);
        acc.z = fmaf(w2, f2b.x, acc.z); acc.w = fmaf(w2, f2b.y, acc.w);
        acc.x = fmaf(w3, f3a.x, acc.x); acc.y = fmaf(w3, f3a.y, acc.y);
        acc.z = fmaf(w3, f3b.x, acc.z); acc.w = fmaf(w3, f3b.y, acc.w);
    }
    for (; i < end; ++i) {
        int2 e = g_edge[i];
        float w = __int_as_float(e.y);
        uint2 p = hh[e.x * 32 + lane];
        float2 fa = __half22float2(*(__half2*)&p.x);
        float2 fb = __half22float2(*(__half2*)&p.y);
        acc.x = fmaf(w, fa.x, acc.x); acc.y = fmaf(w, fa.y, acc.y);
        acc.z = fmaf(w, fb.x, acc.z); acc.w = fmaf(w, fb.y, acc.w);
    }

    float4 aa = ((const float4*)a)[lane];
    acc.x = (acc.x > 0.f) ? acc.x : aa.x * acc.x;
    acc.y = (acc.y > 0.f) ? acc.y : aa.y * acc.y;
    acc.z = (acc.z > 0.f) ? acc.z : aa.z * acc.z;
    acc.w = (acc.w > 0.f) ? acc.w : aa.w * acc.w;

    float4* Z = use_ext ? (float4*)Oext : (float4*)g_z;
    Z[node * 32 + lane] = acc;
}

// -------- launch: prep chain overlapped with splitw + GEMM-1 --------
extern "C" void kernel_launch(void* const* d_in, const int* in_sizes, int n_in,
                              void* d_out, int out_size) {
    const float* x  = (const float*)d_in[0];
    const int*   ei = (const int*)d_in[1];
    const float* ew = (const float*)d_in[2];
    const float* W1 = (const float*)d_in[3];
    const float* b1 = (const float*)d_in[4];
    const float* a1 = (const float*)d_in[5];
    const float* W2 = (const float*)d_in[6];
    const float* b2 = (const float*)d_in[7];
    const float* a2 = (const float*)d_in[8];
    float* out = (float*)d_out;

    const int N = in_sizes[0] / DD;   // 50000
    const int E = in_sizes[2];        // 800000
    const int nb = (N + 1023) / 1024; // 49

    // Side stream + fork/join events (host-side objects only; leaked so the
    // capture that references them stays valid — a handful per process).
    cudaStream_t s2;
    cudaEvent_t evFork, evJoin;
    cudaStreamCreateWithFlags(&s2, cudaStreamNonBlocking);
    cudaEventCreateWithFlags(&evFork, cudaEventDisableTiming);
    cudaEventCreateWithFlags(&evJoin, cudaEventDisableTiming);

    // fork: prep chain on s2
    cudaEventRecord(evFork, 0);
    cudaStreamWaitEvent(s2, evFork, 0);
    k_init   <<<(N + 255) / 256, 256, 0, s2>>>(ei, N);
    k_convert<<<(E + 255) / 256, 256, 0, s2>>>(ei, ew, E);
    k_bsum   <<<nb, 256, 0, s2>>>(N);
    k_bscan  <<<1, 64, 0, s2>>>(nb, N);
    k_rowptr <<<nb, 1024, 0, s2>>>(N);
    k_place  <<<(E + 255) / 256, 256, 0, s2>>>(ew, E);
    cudaEventRecord(evJoin, s2);

    const int gemm_grid = (N + 127) / 128;
    const int agg_grid  = (N * 32 + 255) / 256;

    // concurrent on default stream: W split + layer-1 GEMM
    k_splitw<<<(DD * DD + 255) / 256, 256>>>(W1, W2);
    k_gemm<<<gemm_grid, 256>>>(x, 0, N);

    // join, then the dependent pipeline
    cudaStreamWaitEvent(0, evJoin, 0);
    k_aggregate<<<agg_grid, 256>>>(b1, a1, out, 0, N);
    k_gemm<<<gemm_grid, 256>>>(nullptr, 1, N);
    k_aggregate<<<agg_grid, 256>>>(b2, a2, out, 1, N);
}